// round 11
// baseline (speedup 1.0000x reference)
#include <cuda_runtime.h>
#include <cstdint>
#include <cstddef>

// ---------------------------------------------------------------------------
// GraphSAGE 2-layer, sm_103a.
//   h   = relu( scatter_mean(x, src->dst) @ Wl1^T + bl1 + x @ Wr1^T )
//   out =       scatter_mean(h, src->dst) @ Wl2^T + bl2 + h @ Wr2^T
// Round 10: linearity applied to BOTH layers. Layer 1: zl=x@Wl1^T, zr=x@Wr1^T
// (edge-independent) run on a forked stream CONCURRENTLY with the CSR binning
// chain; then h = relu(mean_gather(zl)+bl1+zr). Layer 2 as before.
// GEMMs: FFMA2 (fma.rn.f32x2), split smem strides (W:130 even, A:133 odd).
// ---------------------------------------------------------------------------

#define MAX_N 100000
#define MAX_E 1600000
#define D_IN  128

typedef unsigned long long ull;

__device__ float g_zl[(size_t)MAX_N * 128];    // layer1 zl; layer2 reuses as z2|r2
__device__ float g_zr[(size_t)MAX_N * 128];
__device__ float g_h[(size_t)MAX_N * 128];
__device__ int   g_bin[MAX_E];
__device__ int   g_cnt[MAX_N + 1];
__device__ int   g_off[MAX_N + 1];
__device__ int   g_cur[MAX_N + 1];
__device__ int   g_bsum[128];
__device__ int   g_is64;

// Stream/event for the fork-join (created at process start, outside any
// capture and outside the harness memory checkpoints; host-side objects).
static cudaStream_t g_s2;
static cudaEvent_t  g_e1, g_e2;
namespace {
struct SideStreamInit {
    SideStreamInit() {
        cudaStreamCreateWithFlags(&g_s2, cudaStreamNonBlocking);
        cudaEventCreateWithFlags(&g_e1, cudaEventDisableTiming);
        cudaEventCreateWithFlags(&g_e2, cudaEventDisableTiming);
    }
} g_side_stream_init;
}

__device__ __forceinline__ void ffma2(ull& d, ull a, ull b) {
    asm("fma.rn.f32x2 %0, %1, %2, %3;" : "=l"(d) : "l"(a), "l"(b), "l"(d));
}
__device__ __forceinline__ void fadd2(ull& d, ull a) {
    asm("add.rn.f32x2 %0, %1, %2;" : "=l"(d) : "l"(a), "l"(d));
}

// ---------------------------------------------------------------------------
__global__ void detect_idx_kernel(const long long* __restrict__ ei, int E, long long N) {
    __shared__ int bad;
    if (threadIdx.x == 0) bad = 0;
    __syncthreads();
    int i = threadIdx.x;
    if (i < E) {
        long long v = ei[i];
        if (v < 0 || v >= N) atomicAdd(&bad, 1);
    }
    __syncthreads();
    if (threadIdx.x == 0) g_is64 = (bad == 0) ? 1 : 0;
}

// ---------------------------------------------------------------------------
// CSR binning: count -> scan -> fill
// ---------------------------------------------------------------------------
__global__ void count_kernel(const void* __restrict__ ei, int* __restrict__ cnt, int E) {
    int i = blockIdx.x * blockDim.x + threadIdx.x;
    if (i >= E) return;
    int d = g_is64 ? (int)((const long long*)ei)[(size_t)E + i]
                   : ((const int*)ei)[(size_t)E + i];
    atomicAdd(&cnt[d], 1);
}

__global__ void scan_block_kernel(const int* __restrict__ cnt, int* __restrict__ off,
                                  int* __restrict__ bsum, int N) {
    __shared__ int sm[1024];
    int tid = threadIdx.x;
    int gi  = blockIdx.x * 1024 + tid;
    int v   = (gi < N) ? cnt[gi] : 0;
    sm[tid] = v;
    __syncthreads();
#pragma unroll
    for (int s = 1; s < 1024; s <<= 1) {
        int t = (tid >= s) ? sm[tid - s] : 0;
        __syncthreads();
        sm[tid] += t;
        __syncthreads();
    }
    if (gi < N) off[gi] = sm[tid] - v;     // exclusive within block
    if (tid == 1023) bsum[blockIdx.x] = sm[1023];
}

// add_off with integrated block-sum prefix (one warp reduces bsum[0..seg)).
__global__ void add_off_kernel(int* __restrict__ off, int* __restrict__ cur,
                               const int* __restrict__ bsum, int N, int E) {
    __shared__ int spref;
    int seg = (blockIdx.x * blockDim.x) >> 10;
    if (threadIdx.x < 32) {
        int s = 0;
        for (int i = threadIdx.x; i < seg; i += 32) s += bsum[i];
#pragma unroll
        for (int o = 16; o; o >>= 1) s += __shfl_down_sync(0xffffffffu, s, o);
        if (threadIdx.x == 0) spref = s;
    }
    __syncthreads();
    int gi = blockIdx.x * blockDim.x + threadIdx.x;
    if (gi < N) {
        int v = off[gi] + spref;
        off[gi] = v;
        cur[gi] = v;
    }
    if (gi == 0) { off[N] = E; cur[N] = E; }
}

__global__ void fill_kernel(const void* __restrict__ ei, int E,
                            int* __restrict__ cur, int* __restrict__ bin) {
    int i = blockIdx.x * blockDim.x + threadIdx.x;
    if (i >= E) return;
    int s, d;
    if (g_is64) {
        const long long* p = (const long long*)ei;
        s = (int)p[i];
        d = (int)p[(size_t)E + i];
    } else {
        const int* p = (const int*)ei;
        s = p[i];
        d = p[(size_t)E + i];
    }
    int pos = atomicAdd(&cur[d], 1);
    bin[pos] = s;
}

// ---------------------------------------------------------------------------
// Gather-mean over 128-wide zl rows + fused epilogue:
//   h = relu(mean + bl1 + zr). One warp per node; lane owns 16B chunk.
// ---------------------------------------------------------------------------
__global__ void gather128_relu_kernel(const ulonglong2* __restrict__ zl,  // 32 u2/row
                                      const int* __restrict__ off,
                                      const int* __restrict__ bin,
                                      const float4* __restrict__ zr,      // 32 f4/row
                                      const float* __restrict__ bias,
                                      float4* __restrict__ h, int N) {
    int node = (blockIdx.x * blockDim.x + threadIdx.x) >> 5;
    int lane = threadIdx.x & 31;
    if (node >= N) return;
    int s0 = off[node], s1 = off[node + 1];
    ull a0 = 0, a1 = 0, a2 = 0, a3 = 0;
    int e = s0;
    int ea = (s0 + 3) & ~3;
    for (; e < s1 && e < ea; e++) {
        ulonglong2 v = zl[(size_t)bin[e] * 32 + lane];
        fadd2(a0, v.x); fadd2(a1, v.y);
    }
    for (; e + 4 <= s1; e += 4) {
        int4 q = *(const int4*)(bin + e);
        ulonglong2 v0 = zl[(size_t)q.x * 32 + lane];
        ulonglong2 v1 = zl[(size_t)q.y * 32 + lane];
        ulonglong2 v2 = zl[(size_t)q.z * 32 + lane];
        ulonglong2 v3 = zl[(size_t)q.w * 32 + lane];
        fadd2(a0, v0.x); fadd2(a1, v0.y);
        fadd2(a2, v1.x); fadd2(a3, v1.y);
        fadd2(a0, v2.x); fadd2(a1, v2.y);
        fadd2(a2, v3.x); fadd2(a3, v3.y);
    }
    for (; e < s1; e++) {
        ulonglong2 v = zl[(size_t)bin[e] * 32 + lane];
        fadd2(a0, v.x); fadd2(a1, v.y);
    }
    fadd2(a0, a2); fadd2(a1, a3);
    float sc = 1.0f / (float)max(s1 - s0, 1);
    float2 p0 = *(float2*)&a0, p1 = *(float2*)&a1;
    float4 rv = zr[(size_t)node * 32 + lane];
    float4 bv = __ldg((const float4*)bias + lane);
    h[(size_t)node * 32 + lane] = make_float4(
        fmaxf(p0.x * sc + bv.x + rv.x, 0.0f),
        fmaxf(p0.y * sc + bv.y + rv.y, 0.0f),
        fmaxf(p1.x * sc + bv.z + rv.z, 0.0f),
        fmaxf(p1.y * sc + bv.w + rv.w, 0.0f));
}

// ---------------------------------------------------------------------------
// Gather-mean over 64-wide z rows + fused epilogue: out = mean + bias + r.
// Half-warp per node; int4 index loads.
// ---------------------------------------------------------------------------
__global__ void gather64_add_kernel(const ulonglong2* __restrict__ z,   // 16 u2/row
                                    const int* __restrict__ off,
                                    const int* __restrict__ bin,
                                    const float4* __restrict__ r,       // 16 f4/row
                                    const float* __restrict__ bias,
                                    float4* __restrict__ out, int N) {
    int warp = (blockIdx.x * blockDim.x + threadIdx.x) >> 5;
    int lane = threadIdx.x & 31;
    int node = warp * 2 + (lane >> 4);
    int l16  = lane & 15;
    if (node >= N) return;
    int s0 = off[node], s1 = off[node + 1];
    ull a0 = 0, a1 = 0, a2 = 0, a3 = 0;
    int e = s0;
    int ea = (s0 + 3) & ~3;
    for (; e < s1 && e < ea; e++) {
        ulonglong2 v = z[(size_t)bin[e] * 16 + l16];
        fadd2(a0, v.x); fadd2(a1, v.y);
    }
    for (; e + 4 <= s1; e += 4) {
        int4 q = *(const int4*)(bin + e);
        ulonglong2 v0 = z[(size_t)q.x * 16 + l16];
        ulonglong2 v1 = z[(size_t)q.y * 16 + l16];
        ulonglong2 v2 = z[(size_t)q.z * 16 + l16];
        ulonglong2 v3 = z[(size_t)q.w * 16 + l16];
        fadd2(a0, v0.x); fadd2(a1, v0.y);
        fadd2(a2, v1.x); fadd2(a3, v1.y);
        fadd2(a0, v2.x); fadd2(a1, v2.y);
        fadd2(a2, v3.x); fadd2(a3, v3.y);
    }
    for (; e < s1; e++) {
        ulonglong2 v = z[(size_t)bin[e] * 16 + l16];
        fadd2(a0, v.x); fadd2(a1, v.y);
    }
    fadd2(a0, a2); fadd2(a1, a3);
    float sc = 1.0f / (float)max(s1 - s0, 1);
    float2 p0 = *(float2*)&a0, p1 = *(float2*)&a1;
    float4 rv = r[(size_t)node * 16 + l16];
    float4 bv = __ldg((const float4*)bias + l16);
    out[(size_t)node * 16 + l16] =
        make_float4(p0.x * sc + bv.x + rv.x, p0.y * sc + bv.y + rv.y,
                    p1.x * sc + bv.z + rv.z, p1.y * sc + bv.w + rv.w);
}

// ---------------------------------------------------------------------------
// Layer-1 split GEMM (K=128): gridDim.y=0 -> zl = x@Wl^T ; y=1 -> zr = x@Wr^T.
// Fully smem-resident (W 64 k-pairs x 128 j; A 64 k-pairs x 128 nodes),
// single stage, one sync. No bias/relu (fused into gather128_relu).
// ---------------------------------------------------------------------------
__global__ void __launch_bounds__(512, 1)
sage_gemm1_split_kernel(const float* __restrict__ x,
                        const float* __restrict__ Wl, const float* __restrict__ Wr,
                        float* __restrict__ zl, float* __restrict__ zr, int N) {
    constexpr int TM  = 128;
    constexpr int TN  = 128;
    constexpr int NT  = 512;
    constexpr int RSW = 130;
    constexpr int RSA = 133;

    extern __shared__ float2 smem2[];
    float2* Wc = smem2;                          // [64][RSW]
    float2* Ac = smem2 + 64 * RSW;               // [64][RSA]

    const int tid   = threadIdx.x;
    const int lane  = tid & 31;
    const int wid   = tid >> 5;
    const int node0 = blockIdx.x * TM;
    const float* W  = (blockIdx.y == 0) ? Wl : Wr;
    float* outp     = (blockIdx.y == 0) ? zl : zr;

    for (int idx = tid; idx < 64 * TN; idx += NT) {
        int j  = idx >> 6;
        int k2 = idx & 63;
        Wc[k2 * RSW + j] = *(const float2*)(W + j * 128 + 2 * k2);
    }

#pragma unroll 4
    for (int idx = tid; idx < (64 * TM) / 2; idx += NT) {
        int k2p  = idx & 31;
        int node = idx >> 5;
        int n    = node0 + node;
        float4 v = make_float4(0.f, 0.f, 0.f, 0.f);
        if (n < N) v = *(const float4*)(x + (size_t)n * 128 + 4 * k2p);
        Ac[(2 * k2p) * RSA + node]     = make_float2(v.x, v.y);
        Ac[(2 * k2p + 1) * RSA + node] = make_float2(v.z, v.w);
    }

    ull acc[4][8];
#pragma unroll
    for (int i = 0; i < 4; i++)
#pragma unroll
        for (int j = 0; j < 8; j++) acc[i][j] = 0ULL;

    __syncthreads();

#pragma unroll 4
    for (int kk2 = 0; kk2 < 64; kk2++) {
        const float2* ar = Ac + kk2 * RSA + lane;
        const float2* wr = Wc + kk2 * RSW + wid * 8;
        ull a[4], w[8];
        a[0] = *(const ull*)(ar);
        a[1] = *(const ull*)(ar + 32);
        a[2] = *(const ull*)(ar + 64);
        a[3] = *(const ull*)(ar + 96);
        ulonglong2 t;
        t = *(const ulonglong2*)(wr);     w[0] = t.x; w[1] = t.y;
        t = *(const ulonglong2*)(wr + 2); w[2] = t.x; w[3] = t.y;
        t = *(const ulonglong2*)(wr + 4); w[4] = t.x; w[5] = t.y;
        t = *(const ulonglong2*)(wr + 6); w[6] = t.x; w[7] = t.y;
#pragma unroll
        for (int i = 0; i < 4; i++)
#pragma unroll
            for (int j = 0; j < 8; j++) ffma2(acc[i][j], a[i], w[j]);
    }

#pragma unroll
    for (int i = 0; i < 4; i++) {
        int n = node0 + lane + 32 * i;
        if (n < N) {
            float rr[8];
#pragma unroll
            for (int j = 0; j < 8; j++) {
                float2 p = *(float2*)&acc[i][j];
                rr[j] = p.x + p.y;
            }
            *(float4*)(outp + (size_t)n * TN + wid * 8)     = make_float4(rr[0], rr[1], rr[2], rr[3]);
            *(float4*)(outp + (size_t)n * TN + wid * 8 + 4) = make_float4(rr[4], rr[5], rr[6], rr[7]);
        }
    }
}

// ---------------------------------------------------------------------------
// Layer-2 dual-output GEMM (K=128):  z = h @ Wl2^T,  r = h @ Wr2^T
// Fully smem-resident, single stage, one sync.
// ---------------------------------------------------------------------------
__global__ void __launch_bounds__(512, 1)
sage_gemm2_kernel(const float* __restrict__ h,
                  const float* __restrict__ Wl, const float* __restrict__ Wr,
                  float* __restrict__ z, float* __restrict__ r, int N) {
    constexpr int TM  = 128;
    constexpr int TN  = 128;
    constexpr int NT  = 512;
    constexpr int RSW = 130;
    constexpr int RSA = 133;

    extern __shared__ float2 smem2[];
    float2* Wc = smem2;                          // [64][RSW]
    float2* Ac = smem2 + 64 * RSW;               // [64][RSA]

    const int tid   = threadIdx.x;
    const int lane  = tid & 31;
    const int wid   = tid >> 5;
    const int node0 = blockIdx.x * TM;

    for (int idx = tid; idx < 64 * TN; idx += NT) {
        int j  = idx >> 6;
        int k2 = idx & 63;
        const float* srcw = (j < 64) ? (Wl + j * 128) : (Wr + (j - 64) * 128);
        Wc[k2 * RSW + j] = *(const float2*)(srcw + 2 * k2);
    }

#pragma unroll 4
    for (int idx = tid; idx < (64 * TM) / 2; idx += NT) {
        int k2p  = idx & 31;
        int node = idx >> 5;
        int n    = node0 + node;
        float4 v = make_float4(0.f, 0.f, 0.f, 0.f);
        if (n < N) v = *(const float4*)(h + (size_t)n * 128 + 4 * k2p);
        Ac[(2 * k2p) * RSA + node]     = make_float2(v.x, v.y);
        Ac[(2 * k2p + 1) * RSA + node] = make_float2(v.z, v.w);
    }

    ull acc[4][8];
#pragma unroll
    for (int i = 0; i < 4; i++)
#pragma unroll
        for (int j = 0; j < 8; j++) acc[i][j] = 0ULL;

    __syncthreads();

#pragma unroll 4
    for (int kk2 = 0; kk2 < 64; kk2++) {
        const float2* ar = Ac + kk2 * RSA + lane;
        const float2* wr = Wc + kk2 * RSW + wid * 8;
        ull a[4], w[8];
        a[0] = *(const ull*)(ar);
        a[1] = *(const ull*)(ar + 32);
        a[2] = *(const ull*)(ar + 64);
        a[3] = *(const ull*)(ar + 96);
        ulonglong2 t;
        t = *(const ulonglong2*)(wr);     w[0] = t.x; w[1] = t.y;
        t = *(const ulonglong2*)(wr + 2); w[2] = t.x; w[3] = t.y;
        t = *(const ulonglong2*)(wr + 4); w[4] = t.x; w[5] = t.y;
        t = *(const ulonglong2*)(wr + 6); w[6] = t.x; w[7] = t.y;
#pragma unroll
        for (int i = 0; i < 4; i++)
#pragma unroll
            for (int j = 0; j < 8; j++) ffma2(acc[i][j], a[i], w[j]);
    }

    const int col  = wid * 8;                    // 0..120
    float* outp    = (col < 64) ? z : r;
    const int colo = (col < 64) ? col : col - 64;

#pragma unroll
    for (int i = 0; i < 4; i++) {
        int n = node0 + lane + 32 * i;
        if (n < N) {
            float rr[8];
#pragma unroll
            for (int j = 0; j < 8; j++) {
                float2 p = *(float2*)&acc[i][j];
                rr[j] = p.x + p.y;
            }
            *(float4*)(outp + (size_t)n * 64 + colo)     = make_float4(rr[0], rr[1], rr[2], rr[3]);
            *(float4*)(outp + (size_t)n * 64 + colo + 4) = make_float4(rr[4], rr[5], rr[6], rr[7]);
        }
    }
}

// ---------------------------------------------------------------------------

extern "C" void kernel_launch(void* const* d_in, const int* in_sizes, int n_in,
                              void* d_out, int out_size) {
    const float* x   = (const float*)d_in[0];
    const void*  ei  = d_in[1];
    const float* Wl1 = (const float*)d_in[2];
    const float* bl1 = (const float*)d_in[3];
    const float* Wr1 = (const float*)d_in[4];
    const float* Wl2 = (const float*)d_in[5];
    const float* bl2 = (const float*)d_in[6];
    const float* Wr2 = (const float*)d_in[7];
    float* out = (float*)d_out;

    int N = in_sizes[0] / D_IN;
    int E = in_sizes[1] / 2;

    float *zl, *zr, *h;
    int *bin, *cnt, *off, *cur, *bsum;
    cudaGetSymbolAddress((void**)&zl,   g_zl);
    cudaGetSymbolAddress((void**)&zr,   g_zr);
    cudaGetSymbolAddress((void**)&h,    g_h);
    cudaGetSymbolAddress((void**)&bin,  g_bin);
    cudaGetSymbolAddress((void**)&cnt,  g_cnt);
    cudaGetSymbolAddress((void**)&off,  g_off);
    cudaGetSymbolAddress((void**)&cur,  g_cur);
    cudaGetSymbolAddress((void**)&bsum, g_bsum);

    float* z2buf = zl;                 // layer-2 z2|r2 reuse zl (dead after gather)
    float* r2buf = zl + (size_t)N * 64;

    constexpr int SMEMG = (64 * 130 + 64 * 133) * 8;       // 134656 B
    cudaFuncSetAttribute(sage_gemm1_split_kernel, cudaFuncAttributeMaxDynamicSharedMemorySize, SMEMG);
    cudaFuncSetAttribute(sage_gemm2_kernel,       cudaFuncAttributeMaxDynamicSharedMemorySize, SMEMG);

    const int TB = 256;
    int nbE = (E + TB - 1) / TB;
    int nbScan = (N + 1023) / 1024;
    int nbGemm = (N + 127) / 128;

    // --- fork: layer-1 GEMMs (edge-independent) on side stream ---
    cudaEventRecord(g_e1, 0);
    cudaStreamWaitEvent(g_s2, g_e1, 0);
    sage_gemm1_split_kernel<<<dim3(nbGemm, 2), 512, SMEMG, g_s2>>>(x, Wl1, Wr1, zl, zr, N);
    cudaEventRecord(g_e2, g_s2);

    // --- main stream: edge normalization + CSR binning (concurrent) ---
    detect_idx_kernel<<<1, 256>>>((const long long*)ei, E, (long long)N);
    cudaMemsetAsync(cnt, 0, (size_t)(N + 1) * sizeof(int));
    count_kernel<<<nbE, TB>>>(ei, cnt, E);
    scan_block_kernel<<<nbScan, 1024>>>(cnt, off, bsum, N);
    add_off_kernel<<<(N + TB - 1) / TB, TB>>>(off, cur, bsum, N, E);
    fill_kernel<<<nbE, TB>>>(ei, E, cur, bin);

    // --- join, then h = relu(mean_gather(zl) + bl1 + zr) ---
    cudaStreamWaitEvent(0, g_e2, 0);
    gather128_relu_kernel<<<(N * 32 + TB - 1) / TB, TB>>>(
        (const ulonglong2*)zl, off, bin, (const float4*)zr, bl1, (float4*)h, N);

    // --- layer 2: transform first, then gather (linearity of mean) ---
    sage_gemm2_kernel<<<nbGemm, 512, SMEMG>>>(h, Wl2, Wr2, z2buf, r2buf, N);
    gather64_add_kernel<<<((N + 1) / 2 * 32 + TB - 1) / TB, TB>>>(
        (const ulonglong2*)z2buf, off, bin, (const float4*)r2buf, bl2, (float4*)out, N);
}

// round 13
// speedup vs baseline: 1.5439x; 1.5439x over previous
#include <cuda_runtime.h>
#include <cuda_fp16.h>
#include <cstdint>
#include <cstddef>

// ---------------------------------------------------------------------------
// GraphSAGE 2-layer, sm_103a.
//   h   = relu( scatter_mean(x, src->dst) @ Wl1^T + bl1 + x @ Wr1^T )
//   out =       scatter_mean(h, src->dst) @ Wl2^T + bl2 + h @ Wr2^T
// Round 12: GEMMs on legacy tensor path (mma.sync m16n8k16 f16 -> f32 acc,
// ldmatrix fragments) — tcgen05 is unavailable (harness PTX targets sm_103,
// not sm_103a). Binning + gathers = exact 441us (R8) configuration.
// ---------------------------------------------------------------------------

#define MAX_N 100000
#define MAX_E 1600000
#define D_IN  128

typedef unsigned long long ull;

__device__ float g_agg[(size_t)MAX_N * 128];   // layer1 agg; layer2 reuses as z2|r2
__device__ float g_h[(size_t)MAX_N * 128];
__device__ int   g_bin[MAX_E];
__device__ int   g_cnt[MAX_N + 1];
__device__ int   g_off[MAX_N + 1];
__device__ int   g_cur[MAX_N + 1];
__device__ int   g_bsum[128];
__device__ int   g_is64;

__device__ __forceinline__ void fadd2(ull& d, ull a) {
    asm("add.rn.f32x2 %0, %1, %2;" : "=l"(d) : "l"(a), "l"(d));
}

__device__ __forceinline__ uint32_t s2u(const void* p) {
    uint32_t a;
    asm("{ .reg .u64 t; cvta.to.shared.u64 t, %1; cvt.u32.u64 %0, t; }"
        : "=r"(a) : "l"(p));
    return a;
}

#define LDSM_X4(d0, d1, d2, d3, addr) \
    asm volatile("ldmatrix.sync.aligned.m8n8.x4.shared.b16 {%0,%1,%2,%3}, [%4];" \
        : "=r"(d0), "=r"(d1), "=r"(d2), "=r"(d3) : "r"(addr))

__device__ __forceinline__ void mma16816(float* c, const uint32_t* a, const uint32_t* b) {
    asm volatile("mma.sync.aligned.m16n8k16.row.col.f32.f16.f16.f32 "
        "{%0,%1,%2,%3}, {%4,%5,%6,%7}, {%8,%9}, {%0,%1,%2,%3};"
        : "+f"(c[0]), "+f"(c[1]), "+f"(c[2]), "+f"(c[3])
        : "r"(a[0]), "r"(a[1]), "r"(a[2]), "r"(a[3]), "r"(b[0]), "r"(b[1]));
}

__device__ __forceinline__ uint4 pack8_f16(float4 f0, float4 f1) {
    __half2 h0 = __floats2half2_rn(f0.x, f0.y), h1 = __floats2half2_rn(f0.z, f0.w);
    __half2 h2 = __floats2half2_rn(f1.x, f1.y), h3 = __floats2half2_rn(f1.z, f1.w);
    uint4 st;
    st.x = *(uint32_t*)&h0; st.y = *(uint32_t*)&h1;
    st.z = *(uint32_t*)&h2; st.w = *(uint32_t*)&h3;
    return st;
}

// ---------------------------------------------------------------------------
__global__ void detect_idx_kernel(const long long* __restrict__ ei, int E, long long N) {
    __shared__ int bad;
    if (threadIdx.x == 0) bad = 0;
    __syncthreads();
    int i = threadIdx.x;
    if (i < E) {
        long long v = ei[i];
        if (v < 0 || v >= N) atomicAdd(&bad, 1);
    }
    __syncthreads();
    if (threadIdx.x == 0) g_is64 = (bad == 0) ? 1 : 0;
}

__global__ void count_kernel(const void* __restrict__ ei, int* __restrict__ cnt, int E) {
    int i = blockIdx.x * blockDim.x + threadIdx.x;
    if (i >= E) return;
    int d = g_is64 ? (int)((const long long*)ei)[(size_t)E + i]
                   : ((const int*)ei)[(size_t)E + i];
    atomicAdd(&cnt[d], 1);
}

__global__ void scan_block_kernel(const int* __restrict__ cnt, int* __restrict__ off,
                                  int* __restrict__ bsum, int N) {
    __shared__ int sm[1024];
    int tid = threadIdx.x;
    int gi  = blockIdx.x * 1024 + tid;
    int v   = (gi < N) ? cnt[gi] : 0;
    sm[tid] = v;
    __syncthreads();
#pragma unroll
    for (int s = 1; s < 1024; s <<= 1) {
        int t = (tid >= s) ? sm[tid - s] : 0;
        __syncthreads();
        sm[tid] += t;
        __syncthreads();
    }
    if (gi < N) off[gi] = sm[tid] - v;
    if (tid == 1023) bsum[blockIdx.x] = sm[1023];
}

__global__ void scan_bsum_kernel(int* __restrict__ bsum, int nb) {
    int lane  = threadIdx.x;
    int carry = 0;
    for (int base = 0; base < nb; base += 32) {
        int i = base + lane;
        int v = (i < nb) ? bsum[i] : 0;
        int orig = v;
#pragma unroll
        for (int s = 1; s < 32; s <<= 1) {
            int t = __shfl_up_sync(0xffffffffu, v, s);
            if (lane >= s) v += t;
        }
        if (i < nb) bsum[i] = carry + v - orig;
        carry += __shfl_sync(0xffffffffu, v, 31);
    }
}

__global__ void add_off_kernel(int* __restrict__ off, int* __restrict__ cur,
                               const int* __restrict__ bsum, int N, int E) {
    int gi = blockIdx.x * blockDim.x + threadIdx.x;
    if (gi < N) {
        int v = off[gi] + bsum[gi >> 10];
        off[gi] = v;
        cur[gi] = v;
    }
    if (gi == 0) { off[N] = E; cur[N] = E; }
}

__global__ void fill_kernel(const void* __restrict__ ei, int E,
                            int* __restrict__ cur, int* __restrict__ bin) {
    int i = blockIdx.x * blockDim.x + threadIdx.x;
    if (i >= E) return;
    int s, d;
    if (g_is64) {
        const long long* p = (const long long*)ei;
        s = (int)p[i];
        d = (int)p[(size_t)E + i];
    } else {
        const int* p = (const int*)ei;
        s = p[i];
        d = p[(size_t)E + i];
    }
    int pos = atomicAdd(&cur[d], 1);
    bin[pos] = s;
}

// ---------------------------------------------------------------------------
// Gather-mean, 128-wide fp32 rows. One warp per node; lane owns 16B chunk.
// ---------------------------------------------------------------------------
__global__ void gather128_kernel(const ulonglong2* __restrict__ feat,
                                 const int* __restrict__ off,
                                 const int* __restrict__ bin,
                                 float4* __restrict__ agg, int N) {
    int node = (blockIdx.x * blockDim.x + threadIdx.x) >> 5;
    int lane = threadIdx.x & 31;
    if (node >= N) return;
    int s0 = off[node], s1 = off[node + 1];
    ull a0 = 0, a1 = 0;
    int e = s0;
    int ea = (s0 + 3) & ~3;
    for (; e < s1 && e < ea; e++) {
        ulonglong2 v = feat[(size_t)bin[e] * 32 + lane];
        fadd2(a0, v.x); fadd2(a1, v.y);
    }
    for (; e + 4 <= s1; e += 4) {
        int4 q = *(const int4*)(bin + e);
        ulonglong2 v0 = feat[(size_t)q.x * 32 + lane];
        ulonglong2 v1 = feat[(size_t)q.y * 32 + lane];
        ulonglong2 v2 = feat[(size_t)q.z * 32 + lane];
        ulonglong2 v3 = feat[(size_t)q.w * 32 + lane];
        fadd2(a0, v0.x); fadd2(a1, v0.y);
        fadd2(a0, v1.x); fadd2(a1, v1.y);
        fadd2(a0, v2.x); fadd2(a1, v2.y);
        fadd2(a0, v3.x); fadd2(a1, v3.y);
    }
    for (; e < s1; e++) {
        ulonglong2 v = feat[(size_t)bin[e] * 32 + lane];
        fadd2(a0, v.x); fadd2(a1, v.y);
    }
    float sc = 1.0f / (float)max(s1 - s0, 1);
    float2 p0 = *(float2*)&a0, p1 = *(float2*)&a1;
    agg[(size_t)node * 32 + lane] =
        make_float4(p0.x * sc, p0.y * sc, p1.x * sc, p1.y * sc);
}

// ---------------------------------------------------------------------------
// Gather-mean over 64-wide z rows + fused epilogue: out = mean + bias + r.
// ---------------------------------------------------------------------------
__global__ void gather64_add_kernel(const ulonglong2* __restrict__ z,
                                    const int* __restrict__ off,
                                    const int* __restrict__ bin,
                                    const float4* __restrict__ r,
                                    const float* __restrict__ bias,
                                    float4* __restrict__ out, int N) {
    int warp = (blockIdx.x * blockDim.x + threadIdx.x) >> 5;
    int lane = threadIdx.x & 31;
    int node = warp * 2 + (lane >> 4);
    int l16  = lane & 15;
    if (node >= N) return;
    int s0 = off[node], s1 = off[node + 1];
    ull a0 = 0, a1 = 0;
    int e = s0;
    int ea = (s0 + 3) & ~3;
    for (; e < s1 && e < ea; e++) {
        ulonglong2 v = z[(size_t)bin[e] * 16 + l16];
        fadd2(a0, v.x); fadd2(a1, v.y);
    }
    for (; e + 4 <= s1; e += 4) {
        int4 q = *(const int4*)(bin + e);
        ulonglong2 v0 = z[(size_t)q.x * 16 + l16];
        ulonglong2 v1 = z[(size_t)q.y * 16 + l16];
        ulonglong2 v2 = z[(size_t)q.z * 16 + l16];
        ulonglong2 v3 = z[(size_t)q.w * 16 + l16];
        fadd2(a0, v0.x); fadd2(a1, v0.y);
        fadd2(a0, v1.x); fadd2(a1, v1.y);
        fadd2(a0, v2.x); fadd2(a1, v2.y);
        fadd2(a0, v3.x); fadd2(a1, v3.y);
    }
    for (; e < s1; e++) {
        ulonglong2 v = z[(size_t)bin[e] * 16 + l16];
        fadd2(a0, v.x); fadd2(a1, v.y);
    }
    float sc = 1.0f / (float)max(s1 - s0, 1);
    float2 p0 = *(float2*)&a0, p1 = *(float2*)&a1;
    float4 rv = r[(size_t)node * 16 + l16];
    float4 bv = __ldg((const float4*)bias + l16);
    out[(size_t)node * 16 + l16] =
        make_float4(p0.x * sc + bv.x + rv.x, p0.y * sc + bv.y + rv.y,
                    p1.x * sc + bv.z + rv.z, p1.y * sc + bv.w + rv.w);
}

// ---------------------------------------------------------------------------
// HMMA GEMM 1 (K=256, f16 in, fp32 acc):
//   h = relu([agg | x] @ [Wl1 ; Wr1]^T + bl1)
// CTA 128x128, 8 warps (4 along M x 2 along N), warp tile 32x64.
// smem: A [128][SA=264] f16, B [128][SA] f16 (stride 264 halves: 132 words
// ≡ 4 mod 32 -> ldmatrix rows hit distinct banks; rows 16B-aligned).
// ---------------------------------------------------------------------------
__global__ void __launch_bounds__(256, 1)
mma_gemm1_kernel(const float* __restrict__ agg, const float* __restrict__ x,
                 const float* __restrict__ Wl, const float* __restrict__ Wr,
                 const float* __restrict__ bias, float* __restrict__ h, int N) {
    constexpr int SA = 264;                      // halves per row
    extern __shared__ __half smemh[];
    __half* As = smemh;                          // [128][SA]
    __half* Bs = smemh + 128 * SA;               // [128][SA]

    const int tid  = threadIdx.x;
    const int warp = tid >> 5;
    const int lane = tid & 31;
    const int wm   = warp & 3;                   // rows wm*32
    const int wn   = warp >> 2;                  // cols wn*64
    const int node0 = blockIdx.x * 128;

    // Stage A = [agg | x]: 128 rows x 256 f16
    for (int c = tid; c < 4096; c += 256) {
        int row = c >> 5;
        int k8  = (c & 31) << 3;
        uint4 st = make_uint4(0u, 0u, 0u, 0u);
        int n = node0 + row;
        if (n < N) {
            const float* s = (k8 < 128) ? (agg + (size_t)n * 128 + k8)
                                        : (x + (size_t)n * 128 + (k8 - 128));
            st = pack8_f16(*(const float4*)s, *(const float4*)(s + 4));
        }
        *(uint4*)(As + row * SA + k8) = st;
    }
    // Stage B = [Wl ; Wr] along K: 128 j-rows x 256 f16
    for (int c = tid; c < 4096; c += 256) {
        int j  = c >> 5;
        int k8 = (c & 31) << 3;
        const float* s = (k8 < 128) ? (Wl + (size_t)j * 128 + k8)
                                    : (Wr + (size_t)j * 128 + (k8 - 128));
        *(uint4*)(Bs + j * SA + k8) = pack8_f16(*(const float4*)s, *(const float4*)(s + 4));
    }
    __syncthreads();

    float acc[2][8][4];
#pragma unroll
    for (int i = 0; i < 2; i++)
#pragma unroll
        for (int j = 0; j < 8; j++)
#pragma unroll
            for (int q = 0; q < 4; q++) acc[i][j][q] = 0.0f;

    const uint32_t smA = s2u(As), smB = s2u(Bs);
    const int arow = (lane & 15);
    const int akh  = 8 * (lane >> 4);
    const int brow = (lane & 7) + 8 * (lane >> 4);
    const int bkh  = 8 * ((lane >> 3) & 1);

#pragma unroll 4
    for (int k0 = 0; k0 < 256; k0 += 16) {
        uint32_t a[2][4];
#pragma unroll
        for (int mt = 0; mt < 2; mt++) {
            int row = wm * 32 + mt * 16 + arow;
            LDSM_X4(a[mt][0], a[mt][1], a[mt][2], a[mt][3],
                    smA + (uint32_t)(row * SA + k0 + akh) * 2);
        }
        uint32_t b[8][2];
#pragma unroll
        for (int p = 0; p < 4; p++) {
            int row = wn * 64 + p * 16 + brow;
            LDSM_X4(b[2 * p][0], b[2 * p][1], b[2 * p + 1][0], b[2 * p + 1][1],
                    smB + (uint32_t)(row * SA + k0 + bkh) * 2);
        }
#pragma unroll
        for (int mt = 0; mt < 2; mt++)
#pragma unroll
            for (int nt = 0; nt < 8; nt++) mma16816(acc[mt][nt], a[mt], b[nt]);
    }

    // Epilogue: c0,c1 -> row t/4, cols 2(t%4); c2,c3 -> row t/4+8
    const int r0 = lane >> 2;
    const int c2 = (lane & 3) * 2;
#pragma unroll
    for (int mt = 0; mt < 2; mt++) {
        int rowA = node0 + wm * 32 + mt * 16 + r0;
        int rowB = rowA + 8;
#pragma unroll
        for (int nt = 0; nt < 8; nt++) {
            int col = wn * 64 + nt * 8 + c2;
            float2 bv = *(const float2*)(bias + col);
            if (rowA < N) {
                float2 v = make_float2(fmaxf(acc[mt][nt][0] + bv.x, 0.0f),
                                       fmaxf(acc[mt][nt][1] + bv.y, 0.0f));
                *(float2*)(h + (size_t)rowA * 128 + col) = v;
            }
            if (rowB < N) {
                float2 v = make_float2(fmaxf(acc[mt][nt][2] + bv.x, 0.0f),
                                       fmaxf(acc[mt][nt][3] + bv.y, 0.0f));
                *(float2*)(h + (size_t)rowB * 128 + col) = v;
            }
        }
    }
}

// ---------------------------------------------------------------------------
// HMMA GEMM 2 (K=128): z = h@Wl2^T, r = h@Wr2^T. B rows j<64 -> Wl2 j,
// j>=64 -> Wr2 j-64. Output cols 0-63 -> z, 64-127 -> r. No bias/relu.
// ---------------------------------------------------------------------------
__global__ void __launch_bounds__(256, 1)
mma_gemm2_kernel(const float* __restrict__ hin,
                 const float* __restrict__ Wl, const float* __restrict__ Wr,
                 float* __restrict__ z, float* __restrict__ r, int N) {
    constexpr int SA = 136;                      // halves per row
    extern __shared__ __half smemh[];
    __half* As = smemh;                          // [128][SA]
    __half* Bs = smemh + 128 * SA;               // [128][SA]

    const int tid  = threadIdx.x;
    const int warp = tid >> 5;
    const int lane = tid & 31;
    const int wm   = warp & 3;
    const int wn   = warp >> 2;
    const int node0 = blockIdx.x * 128;

    for (int c = tid; c < 2048; c += 256) {
        int row = c >> 4;
        int k8  = (c & 15) << 3;
        uint4 st = make_uint4(0u, 0u, 0u, 0u);
        int n = node0 + row;
        if (n < N) {
            const float* s = hin + (size_t)n * 128 + k8;
            st = pack8_f16(*(const float4*)s, *(const float4*)(s + 4));
        }
        *(uint4*)(As + row * SA + k8) = st;
    }
    for (int c = tid; c < 2048; c += 256) {
        int j  = c >> 4;
        int k8 = (c & 15) << 3;
        const float* s = (j < 64) ? (Wl + (size_t)j * 128 + k8)
                                  : (Wr + (size_t)(j - 64) * 128 + k8);
        *(uint4*)(Bs + j * SA + k8) = pack8_f16(*(const float4*)s, *(const float4*)(s + 4));
    }
    __syncthreads();

    float acc[2][8][4];
#pragma unroll
    for (int i = 0; i < 2; i++)
#pragma unroll
        for (int j = 0; j < 8; j++)
#pragma unroll
            for (int q = 0; q < 4; q++) acc[i][j][q] = 0.0f;

    const uint32_t smA = s2u(As), smB = s2u(Bs);
    const int arow = (lane & 15);
    const int akh  = 8 * (lane >> 4);
    const int brow = (lane & 7) + 8 * (lane >> 4);
    const int bkh  = 8 * ((lane >> 3) & 1);

#pragma unroll 4
    for (int k0 = 0; k0 < 128; k0 += 16) {
        uint32_t a[2][4];
#pragma unroll
        for (int mt = 0; mt < 2; mt++) {
            int row = wm * 32 + mt * 16 + arow;
            LDSM_X4(a[mt][0], a[mt][1], a[mt][2], a[mt][3],
                    smA + (uint32_t)(row * SA + k0 + akh) * 2);
        }
        uint32_t b[8][2];
#pragma unroll
        for (int p = 0; p < 4; p++) {
            int row = wn * 64 + p * 16 + brow;
            LDSM_X4(b[2 * p][0], b[2 * p][1], b[2 * p + 1][0], b[2 * p + 1][1],
                    smB + (uint32_t)(row * SA + k0 + bkh) * 2);
        }
#pragma unroll
        for (int mt = 0; mt < 2; mt++)
#pragma unroll
            for (int nt = 0; nt < 8; nt++) mma16816(acc[mt][nt], a[mt], b[nt]);
    }

    const int r0 = lane >> 2;
    const int c2 = (lane & 3) * 2;
#pragma unroll
    for (int mt = 0; mt < 2; mt++) {
        int rowA = node0 + wm * 32 + mt * 16 + r0;
        int rowB = rowA + 8;
#pragma unroll
        for (int nt = 0; nt < 8; nt++) {
            int col = wn * 64 + nt * 8 + c2;
            float* outp = (col < 64) ? z : r;
            int colo = (col < 64) ? col : col - 64;
            if (rowA < N)
                *(float2*)(outp + (size_t)rowA * 64 + colo) =
                    make_float2(acc[mt][nt][0], acc[mt][nt][1]);
            if (rowB < N)
                *(float2*)(outp + (size_t)rowB * 64 + colo) =
                    make_float2(acc[mt][nt][2], acc[mt][nt][3]);
        }
    }
}

// ---------------------------------------------------------------------------

extern "C" void kernel_launch(void* const* d_in, const int* in_sizes, int n_in,
                              void* d_out, int out_size) {
    const float* x   = (const float*)d_in[0];
    const void*  ei  = d_in[1];
    const float* Wl1 = (const float*)d_in[2];
    const float* bl1 = (const float*)d_in[3];
    const float* Wr1 = (const float*)d_in[4];
    const float* Wl2 = (const float*)d_in[5];
    const float* bl2 = (const float*)d_in[6];
    const float* Wr2 = (const float*)d_in[7];
    float* out = (float*)d_out;

    int N = in_sizes[0] / D_IN;
    int E = in_sizes[1] / 2;

    float *agg, *h;
    int *bin, *cnt, *off, *cur, *bsum;
    cudaGetSymbolAddress((void**)&agg,  g_agg);
    cudaGetSymbolAddress((void**)&h,    g_h);
    cudaGetSymbolAddress((void**)&bin,  g_bin);
    cudaGetSymbolAddress((void**)&cnt,  g_cnt);
    cudaGetSymbolAddress((void**)&off,  g_off);
    cudaGetSymbolAddress((void**)&cur,  g_cur);
    cudaGetSymbolAddress((void**)&bsum, g_bsum);

    float* z2buf = agg;                // layer-2 z|r reuse agg (dead after gemm1)
    float* r2buf = agg + (size_t)N * 64;

    constexpr int SMEM_G1 = 2 * 128 * 264 * 2;   // 135168 B
    constexpr int SMEM_G2 = 2 * 128 * 136 * 2;   //  69632 B
    cudaFuncSetAttribute(mma_gemm1_kernel, cudaFuncAttributeMaxDynamicSharedMemorySize, SMEM_G1);
    cudaFuncSetAttribute(mma_gemm2_kernel, cudaFuncAttributeMaxDynamicSharedMemorySize, SMEM_G2);

    const int TB = 256;
    int nbE = (E + TB - 1) / TB;
    int nbScan = (N + 1023) / 1024;
    int nbGemm = (N + 127) / 128;

    // --- edge normalization + CSR binning ---
    detect_idx_kernel<<<1, 256>>>((const long long*)ei, E, (long long)N);
    cudaMemsetAsync(cnt, 0, (size_t)(N + 1) * sizeof(int));
    count_kernel<<<nbE, TB>>>(ei, cnt, E);
    scan_block_kernel<<<nbScan, 1024>>>(cnt, off, bsum, N);
    scan_bsum_kernel<<<1, 32>>>(bsum, nbScan);
    add_off_kernel<<<(N + TB - 1) / TB, TB>>>(off, cur, bsum, N, E);
    fill_kernel<<<nbE, TB>>>(ei, E, cur, bin);

    // --- layer 1 ---
    gather128_kernel<<<(N * 32 + TB - 1) / TB, TB>>>(
        (const ulonglong2*)x, off, bin, (float4*)agg, N);
    mma_gemm1_kernel<<<nbGemm, 256, SMEM_G1>>>(agg, x, Wl1, Wr1, bl1, h, N);

    // --- layer 2: transform first, then gather (linearity of mean) ---
    mma_gemm2_kernel<<<nbGemm, 256, SMEM_G2>>>(h, Wl2, Wr2, z2buf, r2buf, N);
    gather64_add_kernel<<<((N + 1) / 2 * 32 + TB - 1) / TB, TB>>>(
        (const ulonglong2*)z2buf, off, bin, (const float4*)r2buf, bl2, (float4*)out, N);
}

// round 14
// speedup vs baseline: 1.9061x; 1.2346x over previous
#include <cuda_runtime.h>
#include <cuda_fp16.h>
#include <cstdint>
#include <cstddef>

// ---------------------------------------------------------------------------
// GraphSAGE 2-layer, sm_103a.
//   h   = relu( scatter_mean(x, src->dst) @ Wl1^T + bl1 + x @ Wr1^T )
//   out =       scatter_mean(h, src->dst) @ Wl2^T + bl2 + h @ Wr2^T
// Round 13: end-to-end f16 dataflow between kernels (everything the HMMA
// GEMMs consume is f16 anyway): x16 mirror, agg16, h16, z16 all f16; only
// the final residual r and the output stay fp32. Halves every L2 stream the
// (L2-BW-bound) gathers touch. GEMMs: mma.sync m16n8k16 f16->f32.
// ---------------------------------------------------------------------------

#define MAX_N 100000
#define MAX_E 1600000
#define D_IN  128

typedef unsigned long long ull;

__device__ __half g_x16[(size_t)MAX_N * 128];
__device__ __half g_agg16[(size_t)MAX_N * 128];
__device__ __half g_h16[(size_t)MAX_N * 128];
__device__ __half g_z16[(size_t)MAX_N * 64];
__device__ float  g_r[(size_t)MAX_N * 64];
__device__ int    g_bin[MAX_E];
__device__ int    g_cnt[MAX_N + 1];
__device__ int    g_off[MAX_N + 1];
__device__ int    g_cur[MAX_N + 1];
__device__ int    g_bsum[128];
__device__ int    g_is64;

__device__ __forceinline__ void fadd2(ull& d, ull a) {
    asm("add.rn.f32x2 %0, %1, %2;" : "=l"(d) : "l"(a), "l"(d));
}
// accumulate 8 halves (uint4) into 4 packed-f32 accumulators
__device__ __forceinline__ void acc_h8(ull* acc, uint4 v) {
    float2 f0 = __half22float2(*(const __half2*)&v.x);
    float2 f1 = __half22float2(*(const __half2*)&v.y);
    float2 f2 = __half22float2(*(const __half2*)&v.z);
    float2 f3 = __half22float2(*(const __half2*)&v.w);
    fadd2(acc[0], *(ull*)&f0);
    fadd2(acc[1], *(ull*)&f1);
    fadd2(acc[2], *(ull*)&f2);
    fadd2(acc[3], *(ull*)&f3);
}

__device__ __forceinline__ uint32_t s2u(const void* p) {
    uint32_t a;
    asm("{ .reg .u64 t; cvta.to.shared.u64 t, %1; cvt.u32.u64 %0, t; }"
        : "=r"(a) : "l"(p));
    return a;
}

#define LDSM_X4(d0, d1, d2, d3, addr) \
    asm volatile("ldmatrix.sync.aligned.m8n8.x4.shared.b16 {%0,%1,%2,%3}, [%4];" \
        : "=r"(d0), "=r"(d1), "=r"(d2), "=r"(d3) : "r"(addr))

__device__ __forceinline__ void mma16816(float* c, const uint32_t* a, const uint32_t* b) {
    asm volatile("mma.sync.aligned.m16n8k16.row.col.f32.f16.f16.f32 "
        "{%0,%1,%2,%3}, {%4,%5,%6,%7}, {%8,%9}, {%0,%1,%2,%3};"
        : "+f"(c[0]), "+f"(c[1]), "+f"(c[2]), "+f"(c[3])
        : "r"(a[0]), "r"(a[1]), "r"(a[2]), "r"(a[3]), "r"(b[0]), "r"(b[1]));
}

__device__ __forceinline__ uint4 pack8_f16(float4 f0, float4 f1) {
    __half2 h0 = __floats2half2_rn(f0.x, f0.y), h1 = __floats2half2_rn(f0.z, f0.w);
    __half2 h2 = __floats2half2_rn(f1.x, f1.y), h3 = __floats2half2_rn(f1.z, f1.w);
    uint4 st;
    st.x = *(uint32_t*)&h0; st.y = *(uint32_t*)&h1;
    st.z = *(uint32_t*)&h2; st.w = *(uint32_t*)&h3;
    return st;
}

// ---------------------------------------------------------------------------
__global__ void detect_idx_kernel(const long long* __restrict__ ei, int E, long long N) {
    __shared__ int bad;
    if (threadIdx.x == 0) bad = 0;
    __syncthreads();
    int i = threadIdx.x;
    if (i < E) {
        long long v = ei[i];
        if (v < 0 || v >= N) atomicAdd(&bad, 1);
    }
    __syncthreads();
    if (threadIdx.x == 0) g_is64 = (bad == 0) ? 1 : 0;
}

__global__ void count_kernel(const void* __restrict__ ei, int* __restrict__ cnt, int E) {
    int i = blockIdx.x * blockDim.x + threadIdx.x;
    if (i >= E) return;
    int d = g_is64 ? (int)((const long long*)ei)[(size_t)E + i]
                   : ((const int*)ei)[(size_t)E + i];
    atomicAdd(&cnt[d], 1);
}

__global__ void scan_block_kernel(const int* __restrict__ cnt, int* __restrict__ off,
                                  int* __restrict__ bsum, int N) {
    __shared__ int sm[1024];
    int tid = threadIdx.x;
    int gi  = blockIdx.x * 1024 + tid;
    int v   = (gi < N) ? cnt[gi] : 0;
    sm[tid] = v;
    __syncthreads();
#pragma unroll
    for (int s = 1; s < 1024; s <<= 1) {
        int t = (tid >= s) ? sm[tid - s] : 0;
        __syncthreads();
        sm[tid] += t;
        __syncthreads();
    }
    if (gi < N) off[gi] = sm[tid] - v;
    if (tid == 1023) bsum[blockIdx.x] = sm[1023];
}

__global__ void scan_bsum_kernel(int* __restrict__ bsum, int nb) {
    int lane  = threadIdx.x;
    int carry = 0;
    for (int base = 0; base < nb; base += 32) {
        int i = base + lane;
        int v = (i < nb) ? bsum[i] : 0;
        int orig = v;
#pragma unroll
        for (int s = 1; s < 32; s <<= 1) {
            int t = __shfl_up_sync(0xffffffffu, v, s);
            if (lane >= s) v += t;
        }
        if (i < nb) bsum[i] = carry + v - orig;
        carry += __shfl_sync(0xffffffffu, v, 31);
    }
}

__global__ void add_off_kernel(int* __restrict__ off, int* __restrict__ cur,
                               const int* __restrict__ bsum, int N, int E) {
    int gi = blockIdx.x * blockDim.x + threadIdx.x;
    if (gi < N) {
        int v = off[gi] + bsum[gi >> 10];
        off[gi] = v;
        cur[gi] = v;
    }
    if (gi == 0) { off[N] = E; cur[N] = E; }
}

__global__ void fill_kernel(const void* __restrict__ ei, int E,
                            int* __restrict__ cur, int* __restrict__ bin) {
    int i = blockIdx.x * blockDim.x + threadIdx.x;
    if (i >= E) return;
    int s, d;
    if (g_is64) {
        const long long* p = (const long long*)ei;
        s = (int)p[i];
        d = (int)p[(size_t)E + i];
    } else {
        const int* p = (const int*)ei;
        s = p[i];
        d = p[(size_t)E + i];
    }
    int pos = atomicAdd(&cur[d], 1);
    bin[pos] = s;
}

// fp32 -> f16 mirror of x
__global__ void tohalf_kernel(const float2* __restrict__ in, __half2* __restrict__ out, int n2) {
    int i = blockIdx.x * blockDim.x + threadIdx.x;
    if (i < n2) out[i] = __float22half2_rn(in[i]);
}

// ---------------------------------------------------------------------------
// Gather-mean over f16 x rows (256B = 16 lanes x 16B), fp32 accumulate,
// f16 output (agg16). Half-warp per node.
// ---------------------------------------------------------------------------
__global__ void gather128_f16_kernel(const uint4* __restrict__ x16,   // 16 u4/row
                                     const int* __restrict__ off,
                                     const int* __restrict__ bin,
                                     uint4* __restrict__ agg16, int N) {
    int warp = (blockIdx.x * blockDim.x + threadIdx.x) >> 5;
    int lane = threadIdx.x & 31;
    int node = warp * 2 + (lane >> 4);
    int l16  = lane & 15;
    if (node >= N) return;
    int s0 = off[node], s1 = off[node + 1];
    ull acc[4] = {0, 0, 0, 0};
    int e = s0;
    int ea = (s0 + 3) & ~3;
    for (; e < s1 && e < ea; e++)
        acc_h8(acc, x16[(size_t)bin[e] * 16 + l16]);
    for (; e + 4 <= s1; e += 4) {
        int4 q = *(const int4*)(bin + e);
        uint4 v0 = x16[(size_t)q.x * 16 + l16];
        uint4 v1 = x16[(size_t)q.y * 16 + l16];
        uint4 v2 = x16[(size_t)q.z * 16 + l16];
        uint4 v3 = x16[(size_t)q.w * 16 + l16];
        acc_h8(acc, v0); acc_h8(acc, v1); acc_h8(acc, v2); acc_h8(acc, v3);
    }
    for (; e < s1; e++)
        acc_h8(acc, x16[(size_t)bin[e] * 16 + l16]);
    float sc = 1.0f / (float)max(s1 - s0, 1);
    float2 p0 = *(float2*)&acc[0], p1 = *(float2*)&acc[1];
    float2 p2 = *(float2*)&acc[2], p3 = *(float2*)&acc[3];
    agg16[(size_t)node * 16 + l16] = pack8_f16(
        make_float4(p0.x * sc, p0.y * sc, p1.x * sc, p1.y * sc),
        make_float4(p2.x * sc, p2.y * sc, p3.x * sc, p3.y * sc));
}

// ---------------------------------------------------------------------------
// Gather-mean over f16 z rows (128B = 8 lanes x 16B) + fused epilogue:
//   out = mean + bias + r (fp32). Quarter-warp per node.
// ---------------------------------------------------------------------------
__global__ void gather64_f16_add_kernel(const uint4* __restrict__ z16,  // 8 u4/row
                                        const int* __restrict__ off,
                                        const int* __restrict__ bin,
                                        const float4* __restrict__ r,   // 16 f4/row
                                        const float* __restrict__ bias,
                                        float4* __restrict__ out, int N) {
    int warp = (blockIdx.x * blockDim.x + threadIdx.x) >> 5;
    int lane = threadIdx.x & 31;
    int node = warp * 4 + (lane >> 3);
    int l8   = lane & 7;
    if (node >= N) return;
    int s0 = off[node], s1 = off[node + 1];
    ull acc[4] = {0, 0, 0, 0};
    int e = s0;
    int ea = (s0 + 3) & ~3;
    for (; e < s1 && e < ea; e++)
        acc_h8(acc, z16[(size_t)bin[e] * 8 + l8]);
    for (; e + 4 <= s1; e += 4) {
        int4 q = *(const int4*)(bin + e);
        uint4 v0 = z16[(size_t)q.x * 8 + l8];
        uint4 v1 = z16[(size_t)q.y * 8 + l8];
        uint4 v2 = z16[(size_t)q.z * 8 + l8];
        uint4 v3 = z16[(size_t)q.w * 8 + l8];
        acc_h8(acc, v0); acc_h8(acc, v1); acc_h8(acc, v2); acc_h8(acc, v3);
    }
    for (; e < s1; e++)
        acc_h8(acc, z16[(size_t)bin[e] * 8 + l8]);
    float sc = 1.0f / (float)max(s1 - s0, 1);
    float2 p0 = *(float2*)&acc[0], p1 = *(float2*)&acc[1];
    float2 p2 = *(float2*)&acc[2], p3 = *(float2*)&acc[3];
    float4 rv0 = r[(size_t)node * 16 + l8 * 2];
    float4 rv1 = r[(size_t)node * 16 + l8 * 2 + 1];
    float4 bv0 = __ldg((const float4*)bias + l8 * 2);
    float4 bv1 = __ldg((const float4*)bias + l8 * 2 + 1);
    out[(size_t)node * 16 + l8 * 2] =
        make_float4(p0.x * sc + bv0.x + rv0.x, p0.y * sc + bv0.y + rv0.y,
                    p1.x * sc + bv0.z + rv0.z, p1.y * sc + bv0.w + rv0.w);
    out[(size_t)node * 16 + l8 * 2 + 1] =
        make_float4(p2.x * sc + bv1.x + rv1.x, p2.y * sc + bv1.y + rv1.y,
                    p3.x * sc + bv1.z + rv1.z, p3.y * sc + bv1.w + rv1.w);
}

// ---------------------------------------------------------------------------
// HMMA GEMM 1 (K=256): h16 = f16(relu([agg16 | x16] @ [Wl1;Wr1]^T + bl1))
// CTA 128x128, 8 warps (4M x 2N), warp tile 32x64; A/B smem stride 264 halves.
// ---------------------------------------------------------------------------
__global__ void __launch_bounds__(256, 1)
mma_gemm1_kernel(const uint4* __restrict__ agg16, const uint4* __restrict__ x16,
                 const float* __restrict__ Wl, const float* __restrict__ Wr,
                 const float* __restrict__ bias, __half* __restrict__ h16, int N) {
    constexpr int SA = 264;
    extern __shared__ __half smemh[];
    __half* As = smemh;
    __half* Bs = smemh + 128 * SA;

    const int tid  = threadIdx.x;
    const int warp = tid >> 5;
    const int lane = tid & 31;
    const int wm   = warp & 3;
    const int wn   = warp >> 2;
    const int node0 = blockIdx.x * 128;

    // Stage A = [agg16 | x16]: straight f16 copies (no cvt)
    for (int c = tid; c < 4096; c += 256) {
        int row = c >> 5;
        int k8  = (c & 31) << 3;
        uint4 st = make_uint4(0u, 0u, 0u, 0u);
        int n = node0 + row;
        if (n < N)
            st = (k8 < 128) ? agg16[(size_t)n * 16 + (k8 >> 3)]
                            : x16[(size_t)n * 16 + ((k8 - 128) >> 3)];
        *(uint4*)(As + row * SA + k8) = st;
    }
    // Stage B = [Wl ; Wr] (fp32 -> f16)
    for (int c = tid; c < 4096; c += 256) {
        int j  = c >> 5;
        int k8 = (c & 31) << 3;
        const float* s = (k8 < 128) ? (Wl + (size_t)j * 128 + k8)
                                    : (Wr + (size_t)j * 128 + (k8 - 128));
        *(uint4*)(Bs + j * SA + k8) = pack8_f16(*(const float4*)s, *(const float4*)(s + 4));
    }
    __syncthreads();

    float acc[2][8][4];
#pragma unroll
    for (int i = 0; i < 2; i++)
#pragma unroll
        for (int j = 0; j < 8; j++)
#pragma unroll
            for (int q = 0; q < 4; q++) acc[i][j][q] = 0.0f;

    const uint32_t smA = s2u(As), smB = s2u(Bs);
    const int arow = (lane & 15);
    const int akh  = 8 * (lane >> 4);
    const int brow = (lane & 7) + 8 * (lane >> 4);
    const int bkh  = 8 * ((lane >> 3) & 1);

#pragma unroll 4
    for (int k0 = 0; k0 < 256; k0 += 16) {
        uint32_t a[2][4];
#pragma unroll
        for (int mt = 0; mt < 2; mt++) {
            int row = wm * 32 + mt * 16 + arow;
            LDSM_X4(a[mt][0], a[mt][1], a[mt][2], a[mt][3],
                    smA + (uint32_t)(row * SA + k0 + akh) * 2);
        }
        uint32_t b[8][2];
#pragma unroll
        for (int p = 0; p < 4; p++) {
            int row = wn * 64 + p * 16 + brow;
            LDSM_X4(b[2 * p][0], b[2 * p][1], b[2 * p + 1][0], b[2 * p + 1][1],
                    smB + (uint32_t)(row * SA + k0 + bkh) * 2);
        }
#pragma unroll
        for (int mt = 0; mt < 2; mt++)
#pragma unroll
            for (int nt = 0; nt < 8; nt++) mma16816(acc[mt][nt], a[mt], b[nt]);
    }

    const int r0 = lane >> 2;
    const int c2 = (lane & 3) * 2;
#pragma unroll
    for (int mt = 0; mt < 2; mt++) {
        int rowA = node0 + wm * 32 + mt * 16 + r0;
        int rowB = rowA + 8;
#pragma unroll
        for (int nt = 0; nt < 8; nt++) {
            int col = wn * 64 + nt * 8 + c2;
            float2 bv = *(const float2*)(bias + col);
            if (rowA < N) {
                __half2 v = __floats2half2_rn(fmaxf(acc[mt][nt][0] + bv.x, 0.0f),
                                              fmaxf(acc[mt][nt][1] + bv.y, 0.0f));
                *(__half2*)(h16 + (size_t)rowA * 128 + col) = v;
            }
            if (rowB < N) {
                __half2 v = __floats2half2_rn(fmaxf(acc[mt][nt][2] + bv.x, 0.0f),
                                              fmaxf(acc[mt][nt][3] + bv.y, 0.0f));
                *(__half2*)(h16 + (size_t)rowB * 128 + col) = v;
            }
        }
    }
}

// ---------------------------------------------------------------------------
// HMMA GEMM 2 (K=128): z16 = f16(h@Wl2^T), r = h@Wr2^T (fp32).
// ---------------------------------------------------------------------------
__global__ void __launch_bounds__(256, 1)
mma_gemm2_kernel(const uint4* __restrict__ h16,
                 const float* __restrict__ Wl, const float* __restrict__ Wr,
                 __half* __restrict__ z16, float* __restrict__ r, int N) {
    constexpr int SA = 136;
    extern __shared__ __half smemh[];
    __half* As = smemh;
    __half* Bs = smemh + 128 * SA;

    const int tid  = threadIdx.x;
    const int warp = tid >> 5;
    const int lane = tid & 31;
    const int wm   = warp & 3;
    const int wn   = warp >> 2;
    const int node0 = blockIdx.x * 128;

    for (int c = tid; c < 2048; c += 256) {
        int row = c >> 4;
        int k8  = (c & 15) << 3;
        uint4 st = make_uint4(0u, 0u, 0u, 0u);
        int n = node0 + row;
        if (n < N) st = h16[(size_t)n * 16 + (k8 >> 3)];
        *(uint4*)(As + row * SA + k8) = st;
    }
    for (int c = tid; c < 2048; c += 256) {
        int j  = c >> 4;
        int k8 = (c & 15) << 3;
        const float* s = (j < 64) ? (Wl + (size_t)j * 128 + k8)
                                  : (Wr + (size_t)(j - 64) * 128 + k8);
        *(uint4*)(Bs + j * SA + k8) = pack8_f16(*(const float4*)s, *(const float4*)(s + 4));
    }
    __syncthreads();

    float acc[2][8][4];
#pragma unroll
    for (int i = 0; i < 2; i++)
#pragma unroll
        for (int j = 0; j < 8; j++)
#pragma unroll
            for (int q = 0; q < 4; q++) acc[i][j][q] = 0.0f;

    const uint32_t smA = s2u(As), smB = s2u(Bs);
    const int arow = (lane & 15);
    const int akh  = 8 * (lane >> 4);
    const int brow = (lane & 7) + 8 * (lane >> 4);
    const int bkh  = 8 * ((lane >> 3) & 1);

#pragma unroll 4
    for (int k0 = 0; k0 < 128; k0 += 16) {
        uint32_t a[2][4];
#pragma unroll
        for (int mt = 0; mt < 2; mt++) {
            int row = wm * 32 + mt * 16 + arow;
            LDSM_X4(a[mt][0], a[mt][1], a[mt][2], a[mt][3],
                    smA + (uint32_t)(row * SA + k0 + akh) * 2);
        }
        uint32_t b[8][2];
#pragma unroll
        for (int p = 0; p < 4; p++) {
            int row = wn * 64 + p * 16 + brow;
            LDSM_X4(b[2 * p][0], b[2 * p][1], b[2 * p + 1][0], b[2 * p + 1][1],
                    smB + (uint32_t)(row * SA + k0 + bkh) * 2);
        }
#pragma unroll
        for (int mt = 0; mt < 2; mt++)
#pragma unroll
            for (int nt = 0; nt < 8; nt++) mma16816(acc[mt][nt], a[mt], b[nt]);
    }

    const int r0 = lane >> 2;
    const int c2 = (lane & 3) * 2;
#pragma unroll
    for (int mt = 0; mt < 2; mt++) {
        int rowA = node0 + wm * 32 + mt * 16 + r0;
        int rowB = rowA + 8;
#pragma unroll
        for (int nt = 0; nt < 8; nt++) {
            int col = wn * 64 + nt * 8 + c2;
            if (col < 64) {        // -> z16 (f16)
                if (rowA < N)
                    *(__half2*)(z16 + (size_t)rowA * 64 + col) =
                        __floats2half2_rn(acc[mt][nt][0], acc[mt][nt][1]);
                if (rowB < N)
                    *(__half2*)(z16 + (size_t)rowB * 64 + col) =
                        __floats2half2_rn(acc[mt][nt][2], acc[mt][nt][3]);
            } else {               // -> r (fp32)
                int colo = col - 64;
                if (rowA < N)
                    *(float2*)(r + (size_t)rowA * 64 + colo) =
                        make_float2(acc[mt][nt][0], acc[mt][nt][1]);
                if (rowB < N)
                    *(float2*)(r + (size_t)rowB * 64 + colo) =
                        make_float2(acc[mt][nt][2], acc[mt][nt][3]);
            }
        }
    }
}

// ---------------------------------------------------------------------------

extern "C" void kernel_launch(void* const* d_in, const int* in_sizes, int n_in,
                              void* d_out, int out_size) {
    const float* x   = (const float*)d_in[0];
    const void*  ei  = d_in[1];
    const float* Wl1 = (const float*)d_in[2];
    const float* bl1 = (const float*)d_in[3];
    const float* Wr1 = (const float*)d_in[4];
    const float* Wl2 = (const float*)d_in[5];
    const float* bl2 = (const float*)d_in[6];
    const float* Wr2 = (const float*)d_in[7];
    float* out = (float*)d_out;

    int N = in_sizes[0] / D_IN;
    int E = in_sizes[1] / 2;

    __half *x16, *agg16, *h16, *z16;
    float *rbuf;
    int *bin, *cnt, *off, *cur, *bsum;
    cudaGetSymbolAddress((void**)&x16,   g_x16);
    cudaGetSymbolAddress((void**)&agg16, g_agg16);
    cudaGetSymbolAddress((void**)&h16,   g_h16);
    cudaGetSymbolAddress((void**)&z16,   g_z16);
    cudaGetSymbolAddress((void**)&rbuf,  g_r);
    cudaGetSymbolAddress((void**)&bin,   g_bin);
    cudaGetSymbolAddress((void**)&cnt,   g_cnt);
    cudaGetSymbolAddress((void**)&off,   g_off);
    cudaGetSymbolAddress((void**)&cur,   g_cur);
    cudaGetSymbolAddress((void**)&bsum,  g_bsum);

    constexpr int SMEM_G1 = 2 * 128 * 264 * 2;   // 135168 B
    constexpr int SMEM_G2 = 2 * 128 * 136 * 2;   //  69632 B
    cudaFuncSetAttribute(mma_gemm1_kernel, cudaFuncAttributeMaxDynamicSharedMemorySize, SMEM_G1);
    cudaFuncSetAttribute(mma_gemm2_kernel, cudaFuncAttributeMaxDynamicSharedMemorySize, SMEM_G2);

    const int TB = 256;
    int nbE = (E + TB - 1) / TB;
    int nbScan = (N + 1023) / 1024;
    int nbGemm = (N + 127) / 128;

    // --- edge normalization + CSR binning ---
    detect_idx_kernel<<<1, 256>>>((const long long*)ei, E, (long long)N);
    cudaMemsetAsync(cnt, 0, (size_t)(N + 1) * sizeof(int));
    count_kernel<<<nbE, TB>>>(ei, cnt, E);
    scan_block_kernel<<<nbScan, 1024>>>(cnt, off, bsum, N);
    scan_bsum_kernel<<<1, 32>>>(bsum, nbScan);
    add_off_kernel<<<(N + TB - 1) / TB, TB>>>(off, cur, bsum, N, E);
    fill_kernel<<<nbE, TB>>>(ei, E, cur, bin);

    // --- x16 mirror ---
    int n2 = N * 64;
    tohalf_kernel<<<(n2 + TB - 1) / TB, TB>>>((const float2*)x, (__half2*)x16, n2);

    // --- layer 1 ---
    gather128_f16_kernel<<<(((N + 1) / 2) * 32 + TB - 1) / TB, TB>>>(
        (const uint4*)x16, off, bin, (uint4*)agg16, N);
    mma_gemm1_kernel<<<nbGemm, 256, SMEM_G1>>>(
        (const uint4*)agg16, (const uint4*)x16, Wl1, Wr1, bl1, h16, N);

    // --- layer 2: transform first, then gather (linearity of mean) ---
    mma_gemm2_kernel<<<nbGemm, 256, SMEM_G2>>>(
        (const uint4*)h16, Wl2, Wr2, z16, rbuf, N);
    gather64_f16_add_kernel<<<(((N + 3) / 4) * 32 + TB - 1) / TB, TB>>>(
        (const uint4*)z16, off, bin, (const float4*)rbuf, bl2, (float4*)out, N);
}

// round 15
// speedup vs baseline: 2.5041x; 1.3137x over previous
#include <cuda_runtime.h>
#include <cuda_fp16.h>
#include <cstdint>
#include <cstddef>

// ---------------------------------------------------------------------------
// GraphSAGE 2-layer, sm_103a.
//   h   = relu( scatter_mean(x, src->dst) @ Wl1^T + bl1 + x @ Wr1^T )
//   out =       scatter_mean(h, src->dst) @ Wl2^T + bl2 + h @ Wr2^T
// Round 14: GEMM1 K-chunked (69.6KB smem -> 2 CTAs/SM, cross-CTA overlap of
// staging and HMMA), cp.async for all f16 A-staging, scan_bsum folded into
// add_off. Dataflow stays end-to-end f16 (R13): x16/agg16/h16/z16.
// GEMMs: mma.sync m16n8k16 f16 -> fp32 accumulate.
// ---------------------------------------------------------------------------

#define MAX_N 100000
#define MAX_E 1600000
#define D_IN  128

typedef unsigned long long ull;

__device__ __half g_x16[(size_t)MAX_N * 128];
__device__ __half g_agg16[(size_t)MAX_N * 128];
__device__ __half g_h16[(size_t)MAX_N * 128];
__device__ __half g_z16[(size_t)MAX_N * 64];
__device__ float  g_r[(size_t)MAX_N * 64];
__device__ int    g_bin[MAX_E];
__device__ int    g_cnt[MAX_N + 1];
__device__ int    g_off[MAX_N + 1];
__device__ int    g_cur[MAX_N + 1];
__device__ int    g_bsum[128];
__device__ int    g_is64;

__device__ __forceinline__ void fadd2(ull& d, ull a) {
    asm("add.rn.f32x2 %0, %1, %2;" : "=l"(d) : "l"(a), "l"(d));
}
__device__ __forceinline__ void acc_h8(ull* acc, uint4 v) {
    float2 f0 = __half22float2(*(const __half2*)&v.x);
    float2 f1 = __half22float2(*(const __half2*)&v.y);
    float2 f2 = __half22float2(*(const __half2*)&v.z);
    float2 f3 = __half22float2(*(const __half2*)&v.w);
    fadd2(acc[0], *(ull*)&f0);
    fadd2(acc[1], *(ull*)&f1);
    fadd2(acc[2], *(ull*)&f2);
    fadd2(acc[3], *(ull*)&f3);
}

__device__ __forceinline__ uint32_t s2u(const void* p) {
    uint32_t a;
    asm("{ .reg .u64 t; cvta.to.shared.u64 t, %1; cvt.u32.u64 %0, t; }"
        : "=r"(a) : "l"(p));
    return a;
}

#define LDSM_X4(d0, d1, d2, d3, addr) \
    asm volatile("ldmatrix.sync.aligned.m8n8.x4.shared.b16 {%0,%1,%2,%3}, [%4];" \
        : "=r"(d0), "=r"(d1), "=r"(d2), "=r"(d3) : "r"(addr))

__device__ __forceinline__ void mma16816(float* c, const uint32_t* a, const uint32_t* b) {
    asm volatile("mma.sync.aligned.m16n8k16.row.col.f32.f16.f16.f32 "
        "{%0,%1,%2,%3}, {%4,%5,%6,%7}, {%8,%9}, {%0,%1,%2,%3};"
        : "+f"(c[0]), "+f"(c[1]), "+f"(c[2]), "+f"(c[3])
        : "r"(a[0]), "r"(a[1]), "r"(a[2]), "r"(a[3]), "r"(b[0]), "r"(b[1]));
}

// cp.async 16B with zero-fill tail (src-size 0 when out of bounds)
__device__ __forceinline__ void cp_async16(uint32_t dst, const void* src, int szbytes) {
    asm volatile("cp.async.cg.shared.global [%0], [%1], 16, %2;"
                 :: "r"(dst), "l"(src), "r"(szbytes));
}
#define CP_COMMIT() asm volatile("cp.async.commit_group;")
#define CP_WAIT0()  asm volatile("cp.async.wait_group 0;" ::: "memory")

__device__ __forceinline__ uint4 pack8_f16(float4 f0, float4 f1) {
    __half2 h0 = __floats2half2_rn(f0.x, f0.y), h1 = __floats2half2_rn(f0.z, f0.w);
    __half2 h2 = __floats2half2_rn(f1.x, f1.y), h3 = __floats2half2_rn(f1.z, f1.w);
    uint4 st;
    st.x = *(uint32_t*)&h0; st.y = *(uint32_t*)&h1;
    st.z = *(uint32_t*)&h2; st.w = *(uint32_t*)&h3;
    return st;
}

// ---------------------------------------------------------------------------
__global__ void detect_idx_kernel(const long long* __restrict__ ei, int E, long long N) {
    __shared__ int bad;
    if (threadIdx.x == 0) bad = 0;
    __syncthreads();
    int i = threadIdx.x;
    if (i < E) {
        long long v = ei[i];
        if (v < 0 || v >= N) atomicAdd(&bad, 1);
    }
    __syncthreads();
    if (threadIdx.x == 0) g_is64 = (bad == 0) ? 1 : 0;
}

__global__ void count_kernel(const void* __restrict__ ei, int* __restrict__ cnt, int E) {
    int i = blockIdx.x * blockDim.x + threadIdx.x;
    if (i >= E) return;
    int d = g_is64 ? (int)((const long long*)ei)[(size_t)E + i]
                   : ((const int*)ei)[(size_t)E + i];
    atomicAdd(&cnt[d], 1);
}

__global__ void scan_block_kernel(const int* __restrict__ cnt, int* __restrict__ off,
                                  int* __restrict__ bsum, int N) {
    __shared__ int sm[1024];
    int tid = threadIdx.x;
    int gi  = blockIdx.x * 1024 + tid;
    int v   = (gi < N) ? cnt[gi] : 0;
    sm[tid] = v;
    __syncthreads();
#pragma unroll
    for (int s = 1; s < 1024; s <<= 1) {
        int t = (tid >= s) ? sm[tid - s] : 0;
        __syncthreads();
        sm[tid] += t;
        __syncthreads();
    }
    if (gi < N) off[gi] = sm[tid] - v;     // exclusive within block
    if (tid == 1023) bsum[blockIdx.x] = sm[1023];
}

// add_off with integrated block-sum prefix (one warp reduces bsum[0..seg)).
__global__ void add_off_kernel(int* __restrict__ off, int* __restrict__ cur,
                               const int* __restrict__ bsum, int N, int E) {
    __shared__ int spref;
    int seg = (blockIdx.x * blockDim.x) >> 10;
    if (threadIdx.x < 32) {
        int s = 0;
        for (int i = threadIdx.x; i < seg; i += 32) s += bsum[i];
#pragma unroll
        for (int o = 16; o; o >>= 1) s += __shfl_down_sync(0xffffffffu, s, o);
        if (threadIdx.x == 0) spref = s;
    }
    __syncthreads();
    int gi = blockIdx.x * blockDim.x + threadIdx.x;
    if (gi < N) {
        int v = off[gi] + spref;
        off[gi] = v;
        cur[gi] = v;
    }
    if (gi == 0) { off[N] = E; cur[N] = E; }
}

__global__ void fill_kernel(const void* __restrict__ ei, int E,
                            int* __restrict__ cur, int* __restrict__ bin) {
    int i = blockIdx.x * blockDim.x + threadIdx.x;
    if (i >= E) return;
    int s, d;
    if (g_is64) {
        const long long* p = (const long long*)ei;
        s = (int)p[i];
        d = (int)p[(size_t)E + i];
    } else {
        const int* p = (const int*)ei;
        s = p[i];
        d = p[(size_t)E + i];
    }
    int pos = atomicAdd(&cur[d], 1);
    bin[pos] = s;
}

// fp32 -> f16 mirror of x
__global__ void tohalf_kernel(const float2* __restrict__ in, __half2* __restrict__ out, int n2) {
    int i = blockIdx.x * blockDim.x + threadIdx.x;
    if (i < n2) out[i] = __float22half2_rn(in[i]);
}

// ---------------------------------------------------------------------------
// Gather-mean over f16 x rows (256B = 16 lanes x 16B), fp32 accumulate,
// f16 output (agg16). Half-warp per node.
// ---------------------------------------------------------------------------
__global__ void gather128_f16_kernel(const uint4* __restrict__ x16,   // 16 u4/row
                                     const int* __restrict__ off,
                                     const int* __restrict__ bin,
                                     uint4* __restrict__ agg16, int N) {
    int warp = (blockIdx.x * blockDim.x + threadIdx.x) >> 5;
    int lane = threadIdx.x & 31;
    int node = warp * 2 + (lane >> 4);
    int l16  = lane & 15;
    if (node >= N) return;
    int s0 = off[node], s1 = off[node + 1];
    ull acc[4] = {0, 0, 0, 0};
    int e = s0;
    int ea = (s0 + 3) & ~3;
    for (; e < s1 && e < ea; e++)
        acc_h8(acc, x16[(size_t)bin[e] * 16 + l16]);
    for (; e + 4 <= s1; e += 4) {
        int4 q = *(const int4*)(bin + e);
        uint4 v0 = x16[(size_t)q.x * 16 + l16];
        uint4 v1 = x16[(size_t)q.y * 16 + l16];
        uint4 v2 = x16[(size_t)q.z * 16 + l16];
        uint4 v3 = x16[(size_t)q.w * 16 + l16];
        acc_h8(acc, v0); acc_h8(acc, v1); acc_h8(acc, v2); acc_h8(acc, v3);
    }
    for (; e < s1; e++)
        acc_h8(acc, x16[(size_t)bin[e] * 16 + l16]);
    float sc = 1.0f / (float)max(s1 - s0, 1);
    float2 p0 = *(float2*)&acc[0], p1 = *(float2*)&acc[1];
    float2 p2 = *(float2*)&acc[2], p3 = *(float2*)&acc[3];
    agg16[(size_t)node * 16 + l16] = pack8_f16(
        make_float4(p0.x * sc, p0.y * sc, p1.x * sc, p1.y * sc),
        make_float4(p2.x * sc, p2.y * sc, p3.x * sc, p3.y * sc));
}

// ---------------------------------------------------------------------------
// Gather-mean over f16 z rows (128B = 8 lanes x 16B) + fused epilogue:
//   out = mean + bias + r (fp32). Quarter-warp per node.
// ---------------------------------------------------------------------------
__global__ void gather64_f16_add_kernel(const uint4* __restrict__ z16,  // 8 u4/row
                                        const int* __restrict__ off,
                                        const int* __restrict__ bin,
                                        const float4* __restrict__ r,   // 16 f4/row
                                        const float* __restrict__ bias,
                                        float4* __restrict__ out, int N) {
    int warp = (blockIdx.x * blockDim.x + threadIdx.x) >> 5;
    int lane = threadIdx.x & 31;
    int node = warp * 4 + (lane >> 3);
    int l8   = lane & 7;
    if (node >= N) return;
    int s0 = off[node], s1 = off[node + 1];
    ull acc[4] = {0, 0, 0, 0};
    int e = s0;
    int ea = (s0 + 3) & ~3;
    for (; e < s1 && e < ea; e++)
        acc_h8(acc, z16[(size_t)bin[e] * 8 + l8]);
    for (; e + 4 <= s1; e += 4) {
        int4 q = *(const int4*)(bin + e);
        uint4 v0 = z16[(size_t)q.x * 8 + l8];
        uint4 v1 = z16[(size_t)q.y * 8 + l8];
        uint4 v2 = z16[(size_t)q.z * 8 + l8];
        uint4 v3 = z16[(size_t)q.w * 8 + l8];
        acc_h8(acc, v0); acc_h8(acc, v1); acc_h8(acc, v2); acc_h8(acc, v3);
    }
    for (; e < s1; e++)
        acc_h8(acc, z16[(size_t)bin[e] * 8 + l8]);
    float sc = 1.0f / (float)max(s1 - s0, 1);
    float2 p0 = *(float2*)&acc[0], p1 = *(float2*)&acc[1];
    float2 p2 = *(float2*)&acc[2], p3 = *(float2*)&acc[3];
    float4 rv0 = r[(size_t)node * 16 + l8 * 2];
    float4 rv1 = r[(size_t)node * 16 + l8 * 2 + 1];
    float4 bv0 = __ldg((const float4*)bias + l8 * 2);
    float4 bv1 = __ldg((const float4*)bias + l8 * 2 + 1);
    out[(size_t)node * 16 + l8 * 2] =
        make_float4(p0.x * sc + bv0.x + rv0.x, p0.y * sc + bv0.y + rv0.y,
                    p1.x * sc + bv0.z + rv0.z, p1.y * sc + bv0.w + rv0.w);
    out[(size_t)node * 16 + l8 * 2 + 1] =
        make_float4(p2.x * sc + bv1.x + rv1.x, p2.y * sc + bv1.y + rv1.y,
                    p3.x * sc + bv1.z + rv1.z, p3.y * sc + bv1.w + rv1.w);
}

// ---------------------------------------------------------------------------
// HMMA GEMM 1 (K=256, chunked 2x128): h16 = f16(relu([agg16|x16]@[Wl1;Wr1]^T + bl1))
// CTA 128x128, 8 warps (4M x 2N), warp tile 32x64. smem 69.6KB -> 2 CTAs/SM.
// Chunk kc: A from (kc? x16 : agg16) via cp.async; B from (kc? Wr : Wl).
// ---------------------------------------------------------------------------
__global__ void __launch_bounds__(256, 2)
mma_gemm1_kernel(const uint4* __restrict__ agg16, const uint4* __restrict__ x16,
                 const float* __restrict__ Wl, const float* __restrict__ Wr,
                 const float* __restrict__ bias, __half* __restrict__ h16, int N) {
    constexpr int SA = 136;
    extern __shared__ __half smemh[];
    __half* As = smemh;                          // [128][SA]
    __half* Bs = smemh + 128 * SA;               // [128][SA]

    const int tid  = threadIdx.x;
    const int warp = tid >> 5;
    const int lane = tid & 31;
    const int wm   = warp & 3;
    const int wn   = warp >> 2;
    const int node0 = blockIdx.x * 128;

    float acc[2][8][4];
#pragma unroll
    for (int i = 0; i < 2; i++)
#pragma unroll
        for (int j = 0; j < 8; j++)
#pragma unroll
            for (int q = 0; q < 4; q++) acc[i][j][q] = 0.0f;

    const uint32_t smA = s2u(As), smB = s2u(Bs);
    const int arow = (lane & 15);
    const int akh  = 8 * (lane >> 4);
    const int brow = (lane & 7) + 8 * (lane >> 4);
    const int bkh  = 8 * ((lane >> 3) & 1);

#pragma unroll 1
    for (int kc = 0; kc < 2; kc++) {
        // Stage A chunk via cp.async (pure f16 16B copies, zero-fill tail)
        const uint4* srcb = kc ? x16 : agg16;
#pragma unroll
        for (int c = tid; c < 2048; c += 256) {
            int row = c >> 4;
            int u   = c & 15;
            int n   = node0 + row;
            const uint4* src = srcb + ((size_t)(n < N ? n : 0) * 16 + u);
            cp_async16(smA + (uint32_t)(row * SA + u * 8) * 2, src, (n < N) ? 16 : 0);
        }
        CP_COMMIT();
        // Stage B chunk (fp32 -> f16)
        const float* wsrc = kc ? Wr : Wl;
#pragma unroll
        for (int c = tid; c < 2048; c += 256) {
            int j  = c >> 4;
            int k8 = (c & 15) << 3;
            const float* s = wsrc + (size_t)j * 128 + k8;
            *(uint4*)(Bs + j * SA + k8) = pack8_f16(*(const float4*)s, *(const float4*)(s + 4));
        }
        CP_WAIT0();
        __syncthreads();

#pragma unroll 4
        for (int k0 = 0; k0 < 128; k0 += 16) {
            uint32_t a[2][4];
#pragma unroll
            for (int mt = 0; mt < 2; mt++) {
                int row = wm * 32 + mt * 16 + arow;
                LDSM_X4(a[mt][0], a[mt][1], a[mt][2], a[mt][3],
                        smA + (uint32_t)(row * SA + k0 + akh) * 2);
            }
            uint32_t b[8][2];
#pragma unroll
            for (int p = 0; p < 4; p++) {
                int row = wn * 64 + p * 16 + brow;
                LDSM_X4(b[2 * p][0], b[2 * p][1], b[2 * p + 1][0], b[2 * p + 1][1],
                        smB + (uint32_t)(row * SA + k0 + bkh) * 2);
            }
#pragma unroll
            for (int mt = 0; mt < 2; mt++)
#pragma unroll
                for (int nt = 0; nt < 8; nt++) mma16816(acc[mt][nt], a[mt], b[nt]);
        }
        __syncthreads();
    }

    const int r0 = lane >> 2;
    const int c2 = (lane & 3) * 2;
#pragma unroll
    for (int mt = 0; mt < 2; mt++) {
        int rowA = node0 + wm * 32 + mt * 16 + r0;
        int rowB = rowA + 8;
#pragma unroll
        for (int nt = 0; nt < 8; nt++) {
            int col = wn * 64 + nt * 8 + c2;
            float2 bv = *(const float2*)(bias + col);
            if (rowA < N) {
                __half2 v = __floats2half2_rn(fmaxf(acc[mt][nt][0] + bv.x, 0.0f),
                                              fmaxf(acc[mt][nt][1] + bv.y, 0.0f));
                *(__half2*)(h16 + (size_t)rowA * 128 + col) = v;
            }
            if (rowB < N) {
                __half2 v = __floats2half2_rn(fmaxf(acc[mt][nt][2] + bv.x, 0.0f),
                                              fmaxf(acc[mt][nt][3] + bv.y, 0.0f));
                *(__half2*)(h16 + (size_t)rowB * 128 + col) = v;
            }
        }
    }
}

// ---------------------------------------------------------------------------
// HMMA GEMM 2 (K=128): z16 = f16(h@Wl2^T), r = h@Wr2^T (fp32).
// A staged via cp.async from h16. smem 69.6KB, 2 CTAs/SM.
// ---------------------------------------------------------------------------
__global__ void __launch_bounds__(256, 2)
mma_gemm2_kernel(const uint4* __restrict__ h16,
                 const float* __restrict__ Wl, const float* __restrict__ Wr,
                 __half* __restrict__ z16, float* __restrict__ r, int N) {
    constexpr int SA = 136;
    extern __shared__ __half smemh[];
    __half* As = smemh;
    __half* Bs = smemh + 128 * SA;

    const int tid  = threadIdx.x;
    const int warp = tid >> 5;
    const int lane = tid & 31;
    const int wm   = warp & 3;
    const int wn   = warp >> 2;
    const int node0 = blockIdx.x * 128;

    // Stage A via cp.async
#pragma unroll
    for (int c = tid; c < 2048; c += 256) {
        int row = c >> 4;
        int u   = c & 15;
        int n   = node0 + row;
        const uint4* src = h16 + ((size_t)(n < N ? n : 0) * 16 + u);
        cp_async16(s2u(As) + (uint32_t)(row * SA + u * 8) * 2, src, (n < N) ? 16 : 0);
    }
    CP_COMMIT();
    // Stage B
#pragma unroll
    for (int c = tid; c < 2048; c += 256) {
        int j  = c >> 4;
        int k8 = (c & 15) << 3;
        const float* s = (j < 64) ? (Wl + (size_t)j * 128 + k8)
                                  : (Wr + (size_t)(j - 64) * 128 + k8);
        *(uint4*)(Bs + j * SA + k8) = pack8_f16(*(const float4*)s, *(const float4*)(s + 4));
    }
    CP_WAIT0();
    __syncthreads();

    float acc[2][8][4];
#pragma unroll
    for (int i = 0; i < 2; i++)
#pragma unroll
        for (int j = 0; j < 8; j++)
#pragma unroll
            for (int q = 0; q < 4; q++) acc[i][j][q] = 0.0f;

    const uint32_t smA = s2u(As), smB = s2u(Bs);
    const int arow = (lane & 15);
    const int akh  = 8 * (lane >> 4);
    const int brow = (lane & 7) + 8 * (lane >> 4);
    const int bkh  = 8 * ((lane >> 3) & 1);

#pragma unroll 4
    for (int k0 = 0; k0 < 128; k0 += 16) {
        uint32_t a[2][4];
#pragma unroll
        for (int mt = 0; mt < 2; mt++) {
            int row = wm * 32 + mt * 16 + arow;
            LDSM_X4(a[mt][0], a[mt][1], a[mt][2], a[mt][3],
                    smA + (uint32_t)(row * SA + k0 + akh) * 2);
        }
        uint32_t b[8][2];
#pragma unroll
        for (int p = 0; p < 4; p++) {
            int row = wn * 64 + p * 16 + brow;
            LDSM_X4(b[2 * p][0], b[2 * p][1], b[2 * p + 1][0], b[2 * p + 1][1],
                    smB + (uint32_t)(row * SA + k0 + bkh) * 2);
        }
#pragma unroll
        for (int mt = 0; mt < 2; mt++)
#pragma unroll
            for (int nt = 0; nt < 8; nt++) mma16816(acc[mt][nt], a[mt], b[nt]);
    }

    const int r0 = lane >> 2;
    const int c2 = (lane & 3) * 2;
#pragma unroll
    for (int mt = 0; mt < 2; mt++) {
        int rowA = node0 + wm * 32 + mt * 16 + r0;
        int rowB = rowA + 8;
#pragma unroll
        for (int nt = 0; nt < 8; nt++) {
            int col = wn * 64 + nt * 8 + c2;
            if (col < 64) {
                if (rowA < N)
                    *(__half2*)(z16 + (size_t)rowA * 64 + col) =
                        __floats2half2_rn(acc[mt][nt][0], acc[mt][nt][1]);
                if (rowB < N)
                    *(__half2*)(z16 + (size_t)rowB * 64 + col) =
                        __floats2half2_rn(acc[mt][nt][2], acc[mt][nt][3]);
            } else {
                int colo = col - 64;
                if (rowA < N)
                    *(float2*)(r + (size_t)rowA * 64 + colo) =
                        make_float2(acc[mt][nt][0], acc[mt][nt][1]);
                if (rowB < N)
                    *(float2*)(r + (size_t)rowB * 64 + colo) =
                        make_float2(acc[mt][nt][2], acc[mt][nt][3]);
            }
        }
    }
}

// ---------------------------------------------------------------------------

extern "C" void kernel_launch(void* const* d_in, const int* in_sizes, int n_in,
                              void* d_out, int out_size) {
    const float* x   = (const float*)d_in[0];
    const void*  ei  = d_in[1];
    const float* Wl1 = (const float*)d_in[2];
    const float* bl1 = (const float*)d_in[3];
    const float* Wr1 = (const float*)d_in[4];
    const float* Wl2 = (const float*)d_in[5];
    const float* bl2 = (const float*)d_in[6];
    const float* Wr2 = (const float*)d_in[7];
    float* out = (float*)d_out;

    int N = in_sizes[0] / D_IN;
    int E = in_sizes[1] / 2;

    __half *x16, *agg16, *h16, *z16;
    float *rbuf;
    int *bin, *cnt, *off, *cur, *bsum;
    cudaGetSymbolAddress((void**)&x16,   g_x16);
    cudaGetSymbolAddress((void**)&agg16, g_agg16);
    cudaGetSymbolAddress((void**)&h16,   g_h16);
    cudaGetSymbolAddress((void**)&z16,   g_z16);
    cudaGetSymbolAddress((void**)&rbuf,  g_r);
    cudaGetSymbolAddress((void**)&bin,   g_bin);
    cudaGetSymbolAddress((void**)&cnt,   g_cnt);
    cudaGetSymbolAddress((void**)&off,   g_off);
    cudaGetSymbolAddress((void**)&cur,   g_cur);
    cudaGetSymbolAddress((void**)&bsum,  g_bsum);

    constexpr int SMEM_G = 2 * 128 * 136 * 2;    // 69632 B
    cudaFuncSetAttribute(mma_gemm1_kernel, cudaFuncAttributeMaxDynamicSharedMemorySize, SMEM_G);
    cudaFuncSetAttribute(mma_gemm2_kernel, cudaFuncAttributeMaxDynamicSharedMemorySize, SMEM_G);

    const int TB = 256;
    int nbE = (E + TB - 1) / TB;
    int nbScan = (N + 1023) / 1024;
    int nbGemm = (N + 127) / 128;

    // --- edge normalization + CSR binning ---
    cudaMemsetAsync(cnt, 0, (size_t)(N + 1) * sizeof(int));
    detect_idx_kernel<<<1, 256>>>((const long long*)ei, E, (long long)N);
    count_kernel<<<nbE, TB>>>(ei, cnt, E);
    scan_block_kernel<<<nbScan, 1024>>>(cnt, off, bsum, N);
    add_off_kernel<<<(N + TB - 1) / TB, TB>>>(off, cur, bsum, N, E);
    fill_kernel<<<nbE, TB>>>(ei, E, cur, bin);

    // --- x16 mirror ---
    int n2 = N * 64;
    tohalf_kernel<<<(n2 + TB - 1) / TB, TB>>>((const float2*)x, (__half2*)x16, n2);

    // --- layer 1 ---
    gather128_f16_kernel<<<(((N + 1) / 2) * 32 + TB - 1) / TB, TB>>>(
        (const uint4*)x16, off, bin, (uint4*)agg16, N);
    mma_gemm1_kernel<<<nbGemm, 256, SMEM_G>>>(
        (const uint4*)agg16, (const uint4*)x16, Wl1, Wr1, bl1, h16, N);

    // --- layer 2: transform first, then gather (linearity of mean) ---
    mma_gemm2_kernel<<<nbGemm, 256, SMEM_G>>>(
        (const uint4*)h16, Wl2, Wr2, z16, rbuf, N);
    gather64_f16_add_kernel<<<(((N + 3) / 4) * 32 + TB - 1) / TB, TB>>>(
        (const uint4*)z16, off, bin, (const float4*)rbuf, bl2, (float4*)out, N);
}